// round 7
// baseline (speedup 1.0000x reference)
#include <cuda_runtime.h>
#include <math.h>

#define Bsz 4
#define Tq  2048
#define Mm  2048
#define Kk  4096   // Mm + Tq
#define Dm  1024
#define Hh  16
#define Dh  64
#define Ff  4096

// ---------------- scratch (static device globals; no allocation) ----------------
__device__ float g_c   [(size_t)Bsz*Kk*Dm];   // concat(mem, x)
__device__ float g_q   [(size_t)Bsz*Tq*Dm];
__device__ float g_k   [(size_t)Bsz*Kk*Dm];
__device__ float g_v   [(size_t)Bsz*Kk*Dm];
__device__ float g_remb[(size_t)Kk*Dm];
__device__ float g_r   [(size_t)Kk*Dm];
__device__ float g_att [(size_t)Bsz*Tq*Dm];
__device__ float g_proj[(size_t)Bsz*Tq*Dm];
__device__ float g_h   [(size_t)Bsz*Tq*Dm];
__device__ float g_ffn [(size_t)Bsz*Tq*Ff];
__device__ float g_f2  [(size_t)Bsz*Tq*Dm];

// ---------------- concat c = [mem, x] along seq dim ----------------
__global__ void concat_kernel(const float* __restrict__ x, const float* __restrict__ mem) {
    size_t idx = (size_t)blockIdx.x * blockDim.x + threadIdx.x;      // float4 index
    size_t total = (size_t)Bsz * Kk * Dm / 4;
    if (idx >= total) return;
    size_t e = idx * 4;
    size_t row = e / Dm;
    int d = (int)(e % Dm);
    int b = (int)(row / Kk);
    int j = (int)(row % Kk);
    float4 v;
    if (j < Mm) v = *(const float4*)(mem + ((size_t)b*Mm + j)*Dm + d);
    else        v = *(const float4*)(x   + ((size_t)b*Tq + (j-Mm))*Dm + d);
    *(float4*)(g_c + e) = v;
}

// ---------------- sinusoid positional embedding ----------------
__global__ void remb_kernel() {
    size_t idx = (size_t)blockIdx.x * blockDim.x + threadIdx.x;
    if (idx >= (size_t)Kk * Dm) return;
    int j = (int)(idx / Dm);
    int d = (int)(idx % Dm);
    float pos = (float)(Kk - 1 - j);
    int i2 = (d < Dm/2) ? d : d - Dm/2;
    float e = (2.0f * (float)i2) / (float)Dm;
    float invf = 1.0f / powf(10000.0f, e);
    float ang = pos * invf;
    g_remb[idx] = (d < Dm/2) ? sinf(ang) : cosf(ang);
}

// ---------------- generic 128x128x8 SGEMM, double-buffered, 2 CTAs/SM ----------------
// C = A[M,K] @ B[K,N] + bias, opt gelu
__global__ void __launch_bounds__(256, 2)
sgemm_kernel(const float* __restrict__ A, const float* __restrict__ Bm,
             const float* __restrict__ bias, float* __restrict__ C,
             int Mr, int Nr, int Kr, int act) {
    __shared__ float As[2][8][128];
    __shared__ float Bs[2][8][128];
    int tid = threadIdx.x;            // 256 threads
    int tx = tid & 15, ty = tid >> 4; // 16x16, each thread 8x8
    int rowBase = blockIdx.y * 128;
    int nBase   = blockIdx.x * 128;

    float acc[8][8];
#pragma unroll
    for (int i = 0; i < 8; i++)
#pragma unroll
        for (int j = 0; j < 8; j++) acc[i][j] = 0.f;

    int arow = tid >> 1;           // 0..127
    int acol = (tid & 1) * 4;      // 0 or 4
    int brow = tid >> 5;           // 0..7
    int bcol = (tid & 31) * 4;     // 0..124

    const float* Aptr = A + (size_t)(rowBase + arow) * Kr + acol;
    const float* Bptr = Bm + (size_t)brow * Nr + nBase + bcol;

    // prologue: load tile 0 into buffer 0
    {
        float4 av = *(const float4*)(Aptr);
        As[0][acol+0][arow] = av.x;
        As[0][acol+1][arow] = av.y;
        As[0][acol+2][arow] = av.z;
        As[0][acol+3][arow] = av.w;
        float4 bv = *(const float4*)(Bptr);
        *(float4*)&Bs[0][brow][bcol] = bv;
    }
    __syncthreads();

    for (int k0 = 0; k0 < Kr; k0 += 8) {
        int p = (k0 >> 3) & 1;
        bool more = (k0 + 8) < Kr;
        float4 av2, bv2;
        if (more) {   // prefetch next tile into registers (LDG issued before compute)
            av2 = *(const float4*)(Aptr + k0 + 8);
            bv2 = *(const float4*)(Bptr + (size_t)(k0 + 8) * Nr);
        }
#pragma unroll
        for (int kk = 0; kk < 8; kk++) {
            float ar[8], br[8];
            *(float4*)(ar)   = *(float4*)&As[p][kk][ty*8];
            *(float4*)(ar+4) = *(float4*)&As[p][kk][ty*8+4];
            *(float4*)(br)   = *(float4*)&Bs[p][kk][tx*8];
            *(float4*)(br+4) = *(float4*)&Bs[p][kk][tx*8+4];
#pragma unroll
            for (int i = 0; i < 8; i++)
#pragma unroll
                for (int j = 0; j < 8; j++) acc[i][j] += ar[i] * br[j];
        }
        if (more) {
            int q = 1 - p;
            As[q][acol+0][arow] = av2.x;
            As[q][acol+1][arow] = av2.y;
            As[q][acol+2][arow] = av2.z;
            As[q][acol+3][arow] = av2.w;
            *(float4*)&Bs[q][brow][bcol] = bv2;
        }
        __syncthreads();
    }

    const float kG = 0.7978845608028654f;
    float4 bia0 = make_float4(0.f,0.f,0.f,0.f), bia1 = bia0;
    if (bias) {
        bia0 = *(const float4*)(bias + nBase + tx*8);
        bia1 = *(const float4*)(bias + nBase + tx*8 + 4);
    }
#pragma unroll
    for (int i = 0; i < 8; i++) {
        size_t crow = (size_t)(rowBase + ty*8 + i) * Nr + nBase + tx*8;
        float vo[8];
        vo[0] = acc[i][0] + bia0.x; vo[1] = acc[i][1] + bia0.y;
        vo[2] = acc[i][2] + bia0.z; vo[3] = acc[i][3] + bia0.w;
        vo[4] = acc[i][4] + bia1.x; vo[5] = acc[i][5] + bia1.y;
        vo[6] = acc[i][6] + bia1.z; vo[7] = acc[i][7] + bia1.w;
        if (act == 1) {  // tanh-approx gelu (jax default)
#pragma unroll
            for (int j = 0; j < 8; j++) {
                float v = vo[j];
                float v3 = v * v * v;
                vo[j] = 0.5f * v * (1.f + tanhf(kG * (v + 0.044715f * v3)));
            }
        }
        *(float4*)(C + crow)     = make_float4(vo[0], vo[1], vo[2], vo[3]);
        *(float4*)(C + crow + 4) = make_float4(vo[4], vo[5], vo[6], vo[7]);
    }
}

// ---------------- flash-style XL attention ----------------
// grid: (T/64, H, B), 256 threads, dynamic smem
// Pb (64x130 BD band) ALIASES rb (128x65 r band): same 8320-float region.
// rb is dead after the BD GEMM reads it; Pb is written after a barrier.
#define ATT_SMEM_FLOATS (3*64*65 + 8320 + 64*65 + 3*64)   // 25152 floats = 100608 B -> 2 CTAs/SM
__global__ void __launch_bounds__(256, 2)
attn_kernel(const float* __restrict__ q, const float* __restrict__ kg,
            const float* __restrict__ vg, const float* __restrict__ rg,
            const float* __restrict__ uvec, const float* __restrict__ vvec,
            const int* __restrict__ pcausal, float* __restrict__ out) {
    extern __shared__ float sm[];
    float* qu   = sm;                 // 64 x 65
    float* qv   = qu  + 64*65;        // 64 x 65
    float* kt   = qv  + 64*65;        // 64 x 65 (K tile, later V tile)
    float* rbPb = kt  + 64*65;        // 8320 floats: r band (128x65), then BD band (64x130)
    float* Ssm  = rbPb + 8320;        // 64 x 65 (raw AC / probs)
    float* mrow = Ssm + 64*65;        // 64
    float* lrow = mrow + 64;          // 64
    float* arow = lrow + 64;          // 64 (alpha)

    int tid = threadIdx.x;
    int tx = tid & 15, ty = tid >> 4;
    int i0 = blockIdx.x * 64;
    int h  = blockIdx.y;
    int b  = blockIdx.z;
    int causal = *pcausal;

    // load q tile (float4 LDG, scalar STS to keep 65-stride layout)
    for (int idx = tid; idx < 64*16; idx += 256) {
        int i = idx >> 4, d4 = (idx & 15) * 4;
        float4 qv4 = *(const float4*)&q[((size_t)(b*Tq + i0 + i))*Dm + h*Dh + d4];
        float4 uv4 = *(const float4*)&uvec[h*Dh + d4];
        float4 vv4 = *(const float4*)&vvec[h*Dh + d4];
        qu[i*65 + d4+0] = qv4.x + uv4.x;  qu[i*65 + d4+1] = qv4.y + uv4.y;
        qu[i*65 + d4+2] = qv4.z + uv4.z;  qu[i*65 + d4+3] = qv4.w + uv4.w;
        qv[i*65 + d4+0] = qv4.x + vv4.x;  qv[i*65 + d4+1] = qv4.y + vv4.y;
        qv[i*65 + d4+2] = qv4.z + vv4.z;  qv[i*65 + d4+3] = qv4.w + vv4.w;
    }
    if (tid < 64) { mrow[tid] = -1e30f; lrow[tid] = 0.f; }
    float o[4][4] = {};
    __syncthreads();

    int jend = Kk;
    if (causal) { int je = i0 + 63 + Mm + 1; if (je < jend) jend = je; }

    for (int j0 = 0; j0 < jend; j0 += 64) {
        int base = j0 + (Tq - 1) - i0;

        // phase 1: load K tile and r band (float4 LDG)
        for (int idx = tid; idx < 64*16; idx += 256) {
            int j = idx >> 4, d4 = (idx & 15) * 4;
            float4 v = *(const float4*)&kg[((size_t)(b*Kk + j0 + j))*Dm + h*Dh + d4];
            kt[j*65 + d4+0] = v.x; kt[j*65 + d4+1] = v.y;
            kt[j*65 + d4+2] = v.z; kt[j*65 + d4+3] = v.w;
        }
        for (int idx = tid; idx < 128*16; idx += 256) {
            int t = idx >> 4, d4 = (idx & 15) * 4;
            int jr = base - 63 + t;
            jr = jr < 0 ? 0 : (jr > Kk-1 ? Kk-1 : jr);
            float4 v = *(const float4*)&rg[(size_t)jr*Dm + h*Dh + d4];
            rbPb[t*65 + d4+0] = v.x; rbPb[t*65 + d4+1] = v.y;
            rbPb[t*65 + d4+2] = v.z; rbPb[t*65 + d4+3] = v.w;
        }
        __syncthreads();

        // phase 2: AC = qu @ kt^T (64x64), P = qv @ rb^T (64x128 band) -> registers
        float acc1[4][4] = {};
        float accP[4][8] = {};
        for (int d = 0; d < 64; d++) {
            float a1[4], a2[4];
#pragma unroll
            for (int k = 0; k < 4; k++) { a1[k] = qu[(ty*4+k)*65 + d]; a2[k] = qv[(ty*4+k)*65 + d]; }
#pragma unroll
            for (int c = 0; c < 4; c++) {
                float kb = kt[(c*16 + tx)*65 + d];
#pragma unroll
                for (int k = 0; k < 4; k++) acc1[k][c] += a1[k] * kb;
            }
#pragma unroll
            for (int c = 0; c < 8; c++) {
                float rv = rbPb[(c*16 + tx)*65 + d];
#pragma unroll
                for (int k = 0; k < 4; k++) accP[k][c] += a2[k] * rv;
            }
        }
        __syncthreads();   // all GEMM reads of kt/rbPb drained

        // phase 3: write AC -> Ssm, BD band -> rbPb (Pb layout), V -> kt
#pragma unroll
        for (int k = 0; k < 4; k++) {
#pragma unroll
            for (int c = 0; c < 4; c++) Ssm[(ty*4+k)*65 + c*16 + tx] = acc1[k][c];
#pragma unroll
            for (int c = 0; c < 8; c++) rbPb[(ty*4+k)*130 + c*16 + tx] = accP[k][c];
        }
        for (int idx = tid; idx < 64*16; idx += 256) {
            int j = idx >> 4, d4 = (idx & 15) * 4;
            float4 v = *(const float4*)&vg[((size_t)(b*Kk + j0 + j))*Dm + h*Dh + d4];
            kt[j*65 + d4+0] = v.x; kt[j*65 + d4+1] = v.y;
            kt[j*65 + d4+2] = v.z; kt[j*65 + d4+3] = v.w;
        }
        __syncthreads();

        // phase 4: fused combine(AC+BD, scale, mask) + online softmax; probs -> Ssm
        {
            int i = tid >> 2, s4 = tid & 3;
            int ig = i0 + i;
            float sreg[16];
            unsigned maskbits = 0;
            float tmax = -1e30f;
#pragma unroll
            for (int c = 0; c < 16; c++) {
                int j = s4*16 + c;
                int t = j - i + 63;                    // in [0,126]
                float s = (Ssm[i*65 + j] + rbPb[i*130 + t]) * 0.125f;
                bool valid = !(causal && (j0 + j) > ig + Mm);
                if (valid) { maskbits |= (1u << c); tmax = fmaxf(tmax, s); }
                sreg[c] = s;
            }
            tmax = fmaxf(tmax, __shfl_xor_sync(0xffffffffu, tmax, 1));
            tmax = fmaxf(tmax, __shfl_xor_sync(0xffffffffu, tmax, 2));
            float mold = mrow[i];
            float mnew = fmaxf(mold, tmax);
            float psum = 0.f;
#pragma unroll
            for (int c = 0; c < 16; c++) {
                float p = (maskbits & (1u << c)) ? __expf(sreg[c] - mnew) : 0.f;
                Ssm[i*65 + s4*16 + c] = p;
                psum += p;
            }
            psum += __shfl_xor_sync(0xffffffffu, psum, 1);
            psum += __shfl_xor_sync(0xffffffffu, psum, 2);
            if (s4 == 0) {
                float al = __expf(mold - mnew);
                lrow[i] = lrow[i] * al + psum;
                mrow[i] = mnew;
                arow[i] = al;
            }
        }
        __syncthreads();

        // phase 5: o = o*alpha + P @ V
        {
            float al[4];
#pragma unroll
            for (int k = 0; k < 4; k++) al[k] = arow[ty*4 + k];
#pragma unroll
            for (int k = 0; k < 4; k++)
#pragma unroll
                for (int c = 0; c < 4; c++) o[k][c] *= al[k];
            for (int j = 0; j < 64; j++) {
                float p[4];
#pragma unroll
                for (int k = 0; k < 4; k++) p[k] = Ssm[(ty*4+k)*65 + j];
#pragma unroll
                for (int c = 0; c < 4; c++) {
                    float vv = kt[j*65 + c*16 + tx];
#pragma unroll
                    for (int k = 0; k < 4; k++) o[k][c] += p[k] * vv;
                }
            }
        }
        __syncthreads();
    }

#pragma unroll
    for (int k = 0; k < 4; k++) {
        float inv = 1.f / lrow[ty*4 + k];
#pragma unroll
        for (int c = 0; c < 4; c++) {
            out[((size_t)(b*Tq + i0 + ty*4 + k))*Dm + h*Dh + c*16 + tx] = o[k][c] * inv;
        }
    }
}

// ---------------- residual add + layer norm (one block per row) ----------------
__global__ void addln_kernel(const float* __restrict__ a, const float* __restrict__ res,
                             const float* __restrict__ g, const float* __restrict__ bb,
                             float* __restrict__ out) {
    int row = blockIdx.x;
    int tid = threadIdx.x;      // 256
    __shared__ float red1[8], red2[8];
    __shared__ float sMu, sInv;
    float vals[4];
    float s = 0.f, sq = 0.f;
    {
        int d = tid * 4;
        float4 va = *(const float4*)(a  + (size_t)row*Dm + d);
        float4 vr = *(const float4*)(res + (size_t)row*Dm + d);
        vals[0] = va.x + vr.x; vals[1] = va.y + vr.y;
        vals[2] = va.z + vr.z; vals[3] = va.w + vr.w;
#pragma unroll
        for (int k = 0; k < 4; k++) { s += vals[k]; sq += vals[k]*vals[k]; }
    }
#pragma unroll
    for (int off = 16; off; off >>= 1) {
        s  += __shfl_xor_sync(0xffffffffu, s,  off);
        sq += __shfl_xor_sync(0xffffffffu, sq, off);
    }
    if ((tid & 31) == 0) { red1[tid >> 5] = s; red2[tid >> 5] = sq; }
    __syncthreads();
    if (tid == 0) {
        float S = 0.f, Q = 0.f;
        for (int i = 0; i < 8; i++) { S += red1[i]; Q += red2[i]; }
        float mu = S / (float)Dm;
        float var = Q / (float)Dm - mu*mu;
        sMu = mu; sInv = rsqrtf(var + 1e-5f);
    }
    __syncthreads();
    float mu = sMu, inv = sInv;
    {
        int d = tid * 4;
        float4 gg = *(const float4*)(g  + d);
        float4 bv = *(const float4*)(bb + d);
        float4 ov;
        ov.x = (vals[0] - mu) * inv * gg.x + bv.x;
        ov.y = (vals[1] - mu) * inv * gg.y + bv.y;
        ov.z = (vals[2] - mu) * inv * gg.z + bv.z;
        ov.w = (vals[3] - mu) * inv * gg.w + bv.w;
        *(float4*)(out + (size_t)row*Dm + d) = ov;
    }
}

// ---------------- launch ----------------
extern "C" void kernel_launch(void* const* d_in, const int* in_sizes, int n_in,
                              void* d_out, int out_size) {
    const float* x   = (const float*)d_in[0];
    const float* mem = (const float*)d_in[1];
    const float* Wq  = (const float*)d_in[2];
    const float* bq  = (const float*)d_in[3];
    const float* Wk  = (const float*)d_in[4];
    const float* bk  = (const float*)d_in[5];
    const float* Wv  = (const float*)d_in[6];
    const float* bv  = (const float*)d_in[7];
    const float* Wo  = (const float*)d_in[8];
    const float* bo  = (const float*)d_in[9];
    const float* Wr  = (const float*)d_in[10];
    const float* u   = (const float*)d_in[11];
    const float* vv  = (const float*)d_in[12];
    const float* g1  = (const float*)d_in[13];
    const float* be1 = (const float*)d_in[14];
    const float* g2  = (const float*)d_in[15];
    const float* be2 = (const float*)d_in[16];
    const float* W1  = (const float*)d_in[17];
    const float* b1  = (const float*)d_in[18];
    const float* W2  = (const float*)d_in[19];
    const float* b2  = (const float*)d_in[20];
    const int*   pc  = (const int*)  d_in[21];
    float* out = (float*)d_out;

    float *pC, *pQ, *pK, *pV, *pRe, *pR, *pAtt, *pProj, *pH, *pFfn, *pF2;
    cudaGetSymbolAddress((void**)&pC,   g_c);
    cudaGetSymbolAddress((void**)&pQ,   g_q);
    cudaGetSymbolAddress((void**)&pK,   g_k);
    cudaGetSymbolAddress((void**)&pV,   g_v);
    cudaGetSymbolAddress((void**)&pRe,  g_remb);
    cudaGetSymbolAddress((void**)&pR,   g_r);
    cudaGetSymbolAddress((void**)&pAtt, g_att);
    cudaGetSymbolAddress((void**)&pProj,g_proj);
    cudaGetSymbolAddress((void**)&pH,   g_h);
    cudaGetSymbolAddress((void**)&pFfn, g_ffn);
    cudaGetSymbolAddress((void**)&pF2,  g_f2);

    size_t attSmem = (size_t)ATT_SMEM_FLOATS * sizeof(float);
    cudaFuncSetAttribute(attn_kernel, cudaFuncAttributeMaxDynamicSharedMemorySize, (int)attSmem);

    // 1. concat + positional embedding
    {
        size_t tot4 = (size_t)Bsz*Kk*Dm/4;
        concat_kernel<<<(unsigned)((tot4 + 255)/256), 256>>>(x, mem);
        size_t tot = (size_t)Kk*Dm;
        remb_kernel<<<(unsigned)((tot + 255)/256), 256>>>();
    }
    // 2. projections
    sgemm_kernel<<<dim3(Dm/128, (Bsz*Tq)/128), 256>>>(x,   Wq, bq, pQ, Bsz*Tq, Dm, Dm, 0);
    sgemm_kernel<<<dim3(Dm/128, (Bsz*Kk)/128), 256>>>(pC,  Wk, bk, pK, Bsz*Kk, Dm, Dm, 0);
    sgemm_kernel<<<dim3(Dm/128, (Bsz*Kk)/128), 256>>>(pC,  Wv, bv, pV, Bsz*Kk, Dm, Dm, 0);
    sgemm_kernel<<<dim3(Dm/128, Kk/128),        256>>>(pRe, Wr, (const float*)nullptr, pR, Kk, Dm, Dm, 0);
    // 3. attention
    attn_kernel<<<dim3(Tq/64, Hh, Bsz), 256, attSmem>>>(pQ, pK, pV, pR, u, vv, pc, pAtt);
    // 4. output projection + LN1
    sgemm_kernel<<<dim3(Dm/128, (Bsz*Tq)/128), 256>>>(pAtt, Wo, bo, pProj, Bsz*Tq, Dm, Dm, 0);
    addln_kernel<<<Bsz*Tq, 256>>>(pProj, x, g1, be1, pH);
    // 5. FFN + LN2
    sgemm_kernel<<<dim3(Ff/128, (Bsz*Tq)/128), 256>>>(pH,   W1, b1, pFfn, Bsz*Tq, Ff, Dm, 1);
    sgemm_kernel<<<dim3(Dm/128, (Bsz*Tq)/128), 256>>>(pFfn, W2, b2, pF2,  Bsz*Tq, Dm, Ff, 0);
    addln_kernel<<<Bsz*Tq, 256>>>(pF2, pH, g2, be2, out);
}

// round 10
// speedup vs baseline: 2.8525x; 2.8525x over previous
#include <cuda_runtime.h>
#include <math.h>
#include <stdint.h>

#define Bsz 4
#define Tq  2048
#define Mm  2048
#define Kk  4096   // Mm + Tq
#define Dm  1024
#define Hh  16
#define Dh  64
#define Ff  4096

// ---------------- scratch (static device globals; no allocation) ----------------
__device__ float g_c   [(size_t)Bsz*Kk*Dm];   // concat(mem, x)
__device__ float g_q   [(size_t)Bsz*Tq*Dm];
__device__ float g_k   [(size_t)Bsz*Kk*Dm];
__device__ float g_v   [(size_t)Bsz*Kk*Dm];
__device__ float g_remb[(size_t)Kk*Dm];
__device__ float g_r   [(size_t)Kk*Dm];
__device__ float g_att [(size_t)Bsz*Tq*Dm];
__device__ float g_proj[(size_t)Bsz*Tq*Dm];
__device__ float g_h   [(size_t)Bsz*Tq*Dm];
__device__ float g_ffn [(size_t)Bsz*Tq*Ff];
__device__ float g_f2  [(size_t)Bsz*Tq*Dm];

__device__ __forceinline__ uint32_t s2u(const void* p) {
    uint32_t a;
    asm("{ .reg .u64 t; cvta.to.shared.u64 t, %1; cvt.u32.u64 %0, t; }" : "=r"(a) : "l"(p));
    return a;
}
#define CPASYNC16(dst_u32, src_ptr) \
    asm volatile("cp.async.cg.shared.global [%0], [%1], 16;" :: "r"(dst_u32), "l"(src_ptr))
#define CP_COMMIT()  asm volatile("cp.async.commit_group;")
#define CP_WAIT0()   asm volatile("cp.async.wait_group 0;")
#define F2TF32(u, f) asm("cvt.rna.tf32.f32 %0, %1;" : "=r"(u) : "f"(f))
#define MMA_TF32(acc, a, b0, b1)                                               \
    asm volatile("mma.sync.aligned.m16n8k8.row.col.f32.tf32.tf32.f32 "         \
                 "{%0,%1,%2,%3}, {%4,%5,%6,%7}, {%8,%9}, {%0,%1,%2,%3};"       \
                 : "+f"((acc)[0]), "+f"((acc)[1]), "+f"((acc)[2]), "+f"((acc)[3]) \
                 : "r"((a)[0]), "r"((a)[1]), "r"((a)[2]), "r"((a)[3]),         \
                   "r"(b0), "r"(b1))

// ---------------- concat c = [mem, x] along seq dim ----------------
__global__ void concat_kernel(const float* __restrict__ x, const float* __restrict__ mem) {
    size_t idx = (size_t)blockIdx.x * blockDim.x + threadIdx.x;      // float4 index
    size_t total = (size_t)Bsz * Kk * Dm / 4;
    if (idx >= total) return;
    size_t e = idx * 4;
    size_t row = e / Dm;
    int d = (int)(e % Dm);
    int b = (int)(row / Kk);
    int j = (int)(row % Kk);
    float4 v;
    if (j < Mm) v = *(const float4*)(mem + ((size_t)b*Mm + j)*Dm + d);
    else        v = *(const float4*)(x   + ((size_t)b*Tq + (j-Mm))*Dm + d);
    *(float4*)(g_c + e) = v;
}

// ---------------- sinusoid positional embedding ----------------
__global__ void remb_kernel() {
    size_t idx = (size_t)blockIdx.x * blockDim.x + threadIdx.x;
    if (idx >= (size_t)Kk * Dm) return;
    int j = (int)(idx / Dm);
    int d = (int)(idx % Dm);
    float pos = (float)(Kk - 1 - j);
    int i2 = (d < Dm/2) ? d : d - Dm/2;
    float e = (2.0f * (float)i2) / (float)Dm;
    float invf = 1.0f / powf(10000.0f, e);
    float ang = pos * invf;
    g_remb[idx] = (d < Dm/2) ? sinf(ang) : cosf(ang);
}

// ---------------- tf32 tensor-core GEMM: C = A[M,K] @ B[K,N] + bias, opt gelu ----
#define TG_AS_STRIDE 36
#define TG_BS_STRIDE 136
#define TG_AS_BUF (128*TG_AS_STRIDE)        // 4608 floats
#define TG_BS_BUF (32*TG_BS_STRIDE)         // 4352 floats
#define TG_SMEM_FLOATS (2*TG_AS_BUF + 2*TG_BS_BUF)   // 17920 floats = 71680 B
__global__ void __launch_bounds__(256, 2)
tgemm_kernel(const float* __restrict__ A, const float* __restrict__ Bm,
             const float* __restrict__ bias, float* __restrict__ C,
             int Mr, int Nr, int Kr, int act) {
    extern __shared__ float smem[];
    float* AsBase = smem;                     // 2 buffers
    float* BsBase = smem + 2*TG_AS_BUF;
    uint32_t uAs = s2u(AsBase);
    uint32_t uBs = s2u(BsBase);

    int tid  = threadIdx.x;
    int lane = tid & 31, wid = tid >> 5;
    int g = lane >> 2, tig = lane & 3;        // mma group row / thread-in-group
    int warp_m = wid & 3, warp_n = wid >> 2;  // 4 x 2 warp grid
    int rowBase = blockIdx.y * 128;
    int nBase   = blockIdx.x * 128;

    float acc[2][8][4];
#pragma unroll
    for (int mt = 0; mt < 2; mt++)
#pragma unroll
        for (int nt = 0; nt < 8; nt++)
#pragma unroll
            for (int r = 0; r < 4; r++) acc[mt][nt][r] = 0.f;

    int nK = Kr >> 5;   // K-chunks of 32

#define TG_ISSUE(buf, k0)                                                              \
    {                                                                                  \
        uint32_t as = uAs + (uint32_t)(buf)*TG_AS_BUF*4;                               \
        uint32_t bs = uBs + (uint32_t)(buf)*TG_BS_BUF*4;                               \
        _Pragma("unroll")                                                              \
        for (int i = 0; i < 4; i++) {                                                  \
            int idx = tid + i*256;                                                     \
            int row = idx >> 3, kq = (idx & 7) << 2;                                   \
            CPASYNC16(as + (uint32_t)(row*TG_AS_STRIDE + kq)*4,                        \
                      A + (size_t)(rowBase + row)*Kr + (k0) + kq);                     \
        }                                                                              \
        _Pragma("unroll")                                                              \
        for (int i = 0; i < 4; i++) {                                                  \
            int idx = tid + i*256;                                                     \
            int kk2 = idx >> 5, nn = (idx & 31) << 2;                                  \
            CPASYNC16(bs + (uint32_t)(kk2*TG_BS_STRIDE + nn)*4,                        \
                      Bm + (size_t)((k0) + kk2)*Nr + nBase + nn);                      \
        }                                                                              \
        CP_COMMIT();                                                                   \
    }

    TG_ISSUE(0, 0);
    CP_WAIT0();
    __syncthreads();

    for (int kc = 0; kc < nK; kc++) {
        int p = kc & 1;
        if (kc + 1 < nK) TG_ISSUE(p ^ 1, (kc + 1) << 5);

        const float* Asp = AsBase + p*TG_AS_BUF;
        const float* Bsp = BsBase + p*TG_BS_BUF;
        int arow = warp_m*32 + g;
        int ncol = warp_n*64 + g;

#pragma unroll
        for (int ks = 0; ks < 4; ks++) {
            int kk = ks * 8;
            uint32_t bfr[8][2];
#pragma unroll
            for (int nt = 0; nt < 8; nt++) {
                float b0 = Bsp[(kk + tig)*TG_BS_STRIDE + ncol + nt*8];
                float b1 = Bsp[(kk + tig + 4)*TG_BS_STRIDE + ncol + nt*8];
                F2TF32(bfr[nt][0], b0);
                F2TF32(bfr[nt][1], b1);
            }
            uint32_t afr[2][4];
#pragma unroll
            for (int mt = 0; mt < 2; mt++) {
                const float* ap = Asp + (arow + mt*16)*TG_AS_STRIDE + kk + tig;
                float a0 = ap[0];
                float a1 = ap[8*TG_AS_STRIDE];
                float a2 = ap[4];
                float a3 = ap[8*TG_AS_STRIDE + 4];
                F2TF32(afr[mt][0], a0);
                F2TF32(afr[mt][1], a1);
                F2TF32(afr[mt][2], a2);
                F2TF32(afr[mt][3], a3);
            }
#pragma unroll
            for (int mt = 0; mt < 2; mt++)
#pragma unroll
                for (int nt = 0; nt < 8; nt++)
                    MMA_TF32(acc[mt][nt], afr[mt], bfr[nt][0], bfr[nt][1]);
        }

        if (kc + 1 < nK) {
            CP_WAIT0();
            __syncthreads();
        }
    }

    const float kG = 0.7978845608028654f;
#pragma unroll
    for (int mt = 0; mt < 2; mt++) {
        int r0 = rowBase + warp_m*32 + mt*16 + g;
#pragma unroll
        for (int nt = 0; nt < 8; nt++) {
            int c0 = nBase + warp_n*64 + nt*8 + 2*tig;
            float2 bv = make_float2(0.f, 0.f);
            if (bias) bv = *(const float2*)(bias + c0);
            float v[4];
            v[0] = acc[mt][nt][0] + bv.x;
            v[1] = acc[mt][nt][1] + bv.y;
            v[2] = acc[mt][nt][2] + bv.x;
            v[3] = acc[mt][nt][3] + bv.y;
            if (act == 1) {
#pragma unroll
                for (int r = 0; r < 4; r++) {
                    float x = v[r];
                    float x3 = x * x * x;
                    v[r] = 0.5f * x * (1.f + tanhf(kG * (x + 0.044715f * x3)));
                }
            }
            *(float2*)(C + (size_t)r0*Nr + c0)       = make_float2(v[0], v[1]);
            *(float2*)(C + (size_t)(r0 + 8)*Nr + c0) = make_float2(v[2], v[3]);
        }
    }
#undef TG_ISSUE
}

// ---------------- flash-style XL attention (tf32 mma) ----------------
// grid: (T/64, H, B), 256 threads = 8 warps (4 m-blocks x 2 n-halves).
// Strides: 68 (68 mod 32 = 4 -> frag bank = 4g+tig, conflict-free).
// Pb (64x132 BD band) ALIASES rb (128x68): rb dead after BD GEMM reads it.
#define ATT_QS   68
#define ATT_PBS  132
#define ATT_RBPB 8704                        // max(128*68, 64*132)
#define ATT_SMEM_FLOATS (4*64*ATT_QS + ATT_RBPB + 3*64)   // 26304 floats = 105216 B
__global__ void __launch_bounds__(256, 2)
attn_kernel(const float* __restrict__ q, const float* __restrict__ kg,
            const float* __restrict__ vg, const float* __restrict__ rg,
            const float* __restrict__ uvec, const float* __restrict__ vvec,
            const int* __restrict__ pcausal, float* __restrict__ out) {
    extern __shared__ float sm[];
    float* qu   = sm;                        // 64 x 68
    float* qv   = qu  + 64*ATT_QS;           // 64 x 68
    float* kt   = qv  + 64*ATT_QS;           // 64 x 68 (K tile, later V tile)
    float* rbPb = kt  + 64*ATT_QS;           // 8704: r band (128x68) / BD band (64x132)
    float* Ssm  = rbPb + ATT_RBPB;           // 64 x 68 (raw AC / probs)
    float* mrow = Ssm + 64*ATT_QS;           // 64
    float* lrow = mrow + 64;                 // 64
    float* arow = lrow + 64;                 // 64 (alpha)

    int tid  = threadIdx.x;
    int lane = tid & 31, wid = tid >> 5;
    int g = lane >> 2, tig = lane & 3;
    int wm = (wid & 3) * 16;                 // m-block base row (0/16/32/48)
    int wh = wid >> 2;                       // n-half (0/1)
    int i0 = blockIdx.x * 64;
    int h  = blockIdx.y;
    int b  = blockIdx.z;
    int causal = *pcausal;

    // load q tile (float4 LDG, scalar STS, stride 68)
    for (int idx = tid; idx < 64*16; idx += 256) {
        int i = idx >> 4, d4 = (idx & 15) * 4;
        float4 qv4 = *(const float4*)&q[((size_t)(b*Tq + i0 + i))*Dm + h*Dh + d4];
        float4 uv4 = *(const float4*)&uvec[h*Dh + d4];
        float4 vv4 = *(const float4*)&vvec[h*Dh + d4];
        qu[i*ATT_QS + d4+0] = qv4.x + uv4.x;  qu[i*ATT_QS + d4+1] = qv4.y + uv4.y;
        qu[i*ATT_QS + d4+2] = qv4.z + uv4.z;  qu[i*ATT_QS + d4+3] = qv4.w + uv4.w;
        qv[i*ATT_QS + d4+0] = qv4.x + vv4.x;  qv[i*ATT_QS + d4+1] = qv4.y + vv4.y;
        qv[i*ATT_QS + d4+2] = qv4.z + vv4.z;  qv[i*ATT_QS + d4+3] = qv4.w + vv4.w;
    }
    if (tid < 64) { mrow[tid] = -1e30f; lrow[tid] = 0.f; }
    float accO[4][4] = {};                   // PV accumulators (C-frag layout)
    __syncthreads();

    int jend = Kk;
    if (causal) { int je = i0 + 63 + Mm + 1; if (je < jend) jend = je; }

    for (int j0 = 0; j0 < jend; j0 += 64) {
        int base = j0 + (Tq - 1) - i0;

        // phase 1: load K tile and r band
        for (int idx = tid; idx < 64*16; idx += 256) {
            int j = idx >> 4, d4 = (idx & 15) * 4;
            float4 v = *(const float4*)&kg[((size_t)(b*Kk + j0 + j))*Dm + h*Dh + d4];
            kt[j*ATT_QS + d4+0] = v.x; kt[j*ATT_QS + d4+1] = v.y;
            kt[j*ATT_QS + d4+2] = v.z; kt[j*ATT_QS + d4+3] = v.w;
        }
        for (int idx = tid; idx < 128*16; idx += 256) {
            int t = idx >> 4, d4 = (idx & 15) * 4;
            int jr = base - 63 + t;
            jr = jr < 0 ? 0 : (jr > Kk-1 ? Kk-1 : jr);
            float4 v = *(const float4*)&rg[(size_t)jr*Dm + h*Dh + d4];
            rbPb[t*ATT_QS + d4+0] = v.x; rbPb[t*ATT_QS + d4+1] = v.y;
            rbPb[t*ATT_QS + d4+2] = v.z; rbPb[t*ATT_QS + d4+3] = v.w;
        }
        __syncthreads();

        // phase 2: AC = qu @ kt^T (64x64), BD = qv @ rb^T (64x128) via tf32 mma
        float accA[4][4] = {};
        float accB[8][4] = {};
#pragma unroll
        for (int ks = 0; ks < 8; ks++) {
            int kk = ks * 8;
            uint32_t aqu[4], aqv[4];
            {
                const float* p1 = qu + (wm + g)*ATT_QS + kk + tig;
                F2TF32(aqu[0], p1[0]);            F2TF32(aqu[1], p1[8*ATT_QS]);
                F2TF32(aqu[2], p1[4]);            F2TF32(aqu[3], p1[8*ATT_QS + 4]);
                const float* p2 = qv + (wm + g)*ATT_QS + kk + tig;
                F2TF32(aqv[0], p2[0]);            F2TF32(aqv[1], p2[8*ATT_QS]);
                F2TF32(aqv[2], p2[4]);            F2TF32(aqv[3], p2[8*ATT_QS + 4]);
            }
#pragma unroll
            for (int nt = 0; nt < 4; nt++) {
                int jc = wh*32 + nt*8 + g;
                uint32_t b0, b1;
                F2TF32(b0, kt[jc*ATT_QS + kk + tig]);
                F2TF32(b1, kt[jc*ATT_QS + kk + tig + 4]);
                MMA_TF32(accA[nt], aqu, b0, b1);
            }
#pragma unroll
            for (int nt = 0; nt < 8; nt++) {
                int tc = wh*64 + nt*8 + g;
                uint32_t b0, b1;
                F2TF32(b0, rbPb[tc*ATT_QS + kk + tig]);
                F2TF32(b1, rbPb[tc*ATT_QS + kk + tig + 4]);
                MMA_TF32(accB[nt], aqv, b0, b1);
            }
        }
        __syncthreads();   // all reads of kt/rbPb drained

        // phase 3: write AC -> Ssm, BD band -> rbPb (Pb layout), V -> kt
#pragma unroll
        for (int nt = 0; nt < 4; nt++) {
            int col = wh*32 + nt*8 + 2*tig;
            Ssm[(wm + g    )*ATT_QS + col]     = accA[nt][0];
            Ssm[(wm + g    )*ATT_QS + col + 1] = accA[nt][1];
            Ssm[(wm + g + 8)*ATT_QS + col]     = accA[nt][2];
            Ssm[(wm + g + 8)*ATT_QS + col + 1] = accA[nt][3];
        }
#pragma unroll
        for (int nt = 0; nt < 8; nt++) {
            int col = wh*64 + nt*8 + 2*tig;
            rbPb[(wm + g    )*ATT_PBS + col]     = accB[nt][0];
            rbPb[(wm + g    )*ATT_PBS + col + 1] = accB[nt][1];
            rbPb[(wm + g + 8)*ATT_PBS + col]     = accB[nt][2];
            rbPb[(wm + g + 8)*ATT_PBS + col + 1] = accB[nt][3];
        }
        for (int idx = tid; idx < 64*16; idx += 256) {
            int j = idx >> 4, d4 = (idx & 15) * 4;
            float4 v = *(const float4*)&vg[((size_t)(b*Kk + j0 + j))*Dm + h*Dh + d4];
            kt[j*ATT_QS + d4+0] = v.x; kt[j*ATT_QS + d4+1] = v.y;
            kt[j*ATT_QS + d4+2] = v.z; kt[j*ATT_QS + d4+3] = v.w;
        }
        __syncthreads();

        // phase 4: fused combine(AC+BD, scale, mask) + online softmax; probs -> Ssm
        {
            int i = tid >> 2, s4 = tid & 3;
            int ig = i0 + i;
            float sreg[16];
            unsigned maskbits = 0;
            float tmax = -1e30f;
#pragma unroll
            for (int c = 0; c < 16; c++) {
                int j = s4*16 + c;
                int t = j - i + 63;                    // in [0,126]
                float s = (Ssm[i*ATT_QS + j] + rbPb[i*ATT_PBS + t]) * 0.125f;
                bool valid = !(causal && (j0 + j) > ig + Mm);
                if (valid) { maskbits |= (1u << c); tmax = fmaxf(tmax, s); }
                sreg[c] = s;
            }
            tmax = fmaxf(tmax, __shfl_xor_sync(0xffffffffu, tmax, 1));
            tmax = fmaxf(tmax, __shfl_xor_sync(0xffffffffu, tmax, 2));
            float mold = mrow[i];
            float mnew = fmaxf(mold, tmax);
            float psum = 0.f;
#pragma unroll
            for (int c = 0; c < 16; c++) {
                float p = (maskbits & (1u << c)) ? __expf(sreg[c] - mnew) : 0.f;
                Ssm[i*ATT_QS + s4*16 + c] = p;
                psum += p;
            }
            psum += __shfl_xor_sync(0xffffffffu, psum, 1);
            psum += __shfl_xor_sync(0xffffffffu, psum, 2);
            if (s4 == 0) {
                float al = __expf(mold - mnew);
                lrow[i] = lrow[i] * al + psum;
                mrow[i] = mnew;
                arow[i] = al;
            }
        }
        __syncthreads();

        // phase 5: accO = accO*alpha + P @ V via tf32 mma
        {
            float alA = arow[wm + g], alB = arow[wm + g + 8];
#pragma unroll
            for (int nt = 0; nt < 4; nt++) {
                accO[nt][0] *= alA; accO[nt][1] *= alA;
                accO[nt][2] *= alB; accO[nt][3] *= alB;
            }
#pragma unroll
            for (int ks = 0; ks < 8; ks++) {
                int kk = ks * 8;
                uint32_t ap[4];
                const float* pp = Ssm + (wm + g)*ATT_QS + kk + tig;
                F2TF32(ap[0], pp[0]);            F2TF32(ap[1], pp[8*ATT_QS]);
                F2TF32(ap[2], pp[4]);            F2TF32(ap[3], pp[8*ATT_QS + 4]);
#pragma unroll
                for (int nt = 0; nt < 4; nt++) {
                    int dc = wh*32 + nt*8 + g;
                    uint32_t b0, b1;
                    F2TF32(b0, kt[(kk + tig    )*ATT_QS + dc]);
                    F2TF32(b1, kt[(kk + tig + 4)*ATT_QS + dc]);
                    MMA_TF32(accO[nt], ap, b0, b1);
                }
            }
        }
        __syncthreads();
    }

    // final write: normalize by lrow
    {
        float invA = 1.f / lrow[wm + g];
        float invB = 1.f / lrow[wm + g + 8];
#pragma unroll
        for (int nt = 0; nt < 4; nt++) {
            int col = h*Dh + wh*32 + nt*8 + 2*tig;
            size_t rA = ((size_t)(b*Tq + i0 + wm + g    ))*Dm + col;
            size_t rB = ((size_t)(b*Tq + i0 + wm + g + 8))*Dm + col;
            out[rA]     = accO[nt][0] * invA;
            out[rA + 1] = accO[nt][1] * invA;
            out[rB]     = accO[nt][2] * invB;
            out[rB + 1] = accO[nt][3] * invB;
        }
    }
}

// ---------------- residual add + layer norm (one block per row) ----------------
__global__ void addln_kernel(const float* __restrict__ a, const float* __restrict__ res,
                             const float* __restrict__ g, const float* __restrict__ bb,
                             float* __restrict__ out) {
    int row = blockIdx.x;
    int tid = threadIdx.x;      // 256
    __shared__ float red1[8], red2[8];
    __shared__ float sMu, sInv;
    float vals[4];
    float s = 0.f, sq = 0.f;
    {
        int d = tid * 4;
        float4 va = *(const float4*)(a  + (size_t)row*Dm + d);
        float4 vr = *(const float4*)(res + (size_t)row*Dm + d);
        vals[0] = va.x + vr.x; vals[1] = va.y + vr.y;
        vals[2] = va.z + vr.z; vals[3] = va.w + vr.w;
#pragma unroll
        for (int k = 0; k < 4; k++) { s += vals[k]; sq += vals[k]*vals[k]; }
    }
#pragma unroll
    for (int off = 16; off; off >>= 1) {
        s  += __shfl_xor_sync(0xffffffffu, s,  off);
        sq += __shfl_xor_sync(0xffffffffu, sq, off);
    }
    if ((tid & 31) == 0) { red1[tid >> 5] = s; red2[tid >> 5] = sq; }
    __syncthreads();
    if (tid == 0) {
        float S = 0.f, Q = 0.f;
        for (int i = 0; i < 8; i++) { S += red1[i]; Q += red2[i]; }
        float mu = S / (float)Dm;
        float var = Q / (float)Dm - mu*mu;
        sMu = mu; sInv = rsqrtf(var + 1e-5f);
    }
    __syncthreads();
    float mu = sMu, inv = sInv;
    {
        int d = tid * 4;
        float4 gg = *(const float4*)(g  + d);
        float4 bv = *(const float4*)(bb + d);
        float4 ov;
        ov.x = (vals[0] - mu) * inv * gg.x + bv.x;
        ov.y = (vals[1] - mu) * inv * gg.y + bv.y;
        ov.z = (vals[2] - mu) * inv * gg.z + bv.z;
        ov.w = (vals[3] - mu) * inv * gg.w + bv.w;
        *(float4*)(out + (size_t)row*Dm + d) = ov;
    }
}

// ---------------- launch ----------------
extern "C" void kernel_launch(void* const* d_in, const int* in_sizes, int n_in,
                              void* d_out, int out_size) {
    const float* x   = (const float*)d_in[0];
    const float* mem = (const float*)d_in[1];
    const float* Wq  = (const float*)d_in[2];
    const float* bq  = (const float*)d_in[3];
    const float* Wk  = (const float*)d_in[4];
    const float* bk  = (const float*)d_in[5];
    const float* Wv  = (const float*)d_in[6];
    const float* bv  = (const float*)d_in[7];
    const float* Wo  = (const float*)d_in[8];
    const float* bo  = (const float*)d_in[9];
    const float* Wr  = (const float*)d_in[10];
    const float* u   = (const float*)d_in[11];
    const float* vv  = (const float*)d_in[12];
    const float* g1  = (const float*)d_in[13];
    const float* be1 = (const float*)d_in[14];
    const float* g2  = (const float*)d_in[15];
    const float* be2 = (const float*)d_in[16];
    const float* W1  = (const float*)d_in[17];
    const float* b1  = (const float*)d_in[18];
    const float* W2  = (const float*)d_in[19];
    const float* b2  = (const float*)d_in[20];
    const int*   pc  = (const int*)  d_in[21];
    float* out = (float*)d_out;

    float *pC, *pQ, *pK, *pV, *pRe, *pR, *pAtt, *pProj, *pH, *pFfn, *pF2;
    cudaGetSymbolAddress((void**)&pC,   g_c);
    cudaGetSymbolAddress((void**)&pQ,   g_q);
    cudaGetSymbolAddress((void**)&pK,   g_k);
    cudaGetSymbolAddress((void**)&pV,   g_v);
    cudaGetSymbolAddress((void**)&pRe,  g_remb);
    cudaGetSymbolAddress((void**)&pR,   g_r);
    cudaGetSymbolAddress((void**)&pAtt, g_att);
    cudaGetSymbolAddress((void**)&pProj,g_proj);
    cudaGetSymbolAddress((void**)&pH,   g_h);
    cudaGetSymbolAddress((void**)&pFfn, g_ffn);
    cudaGetSymbolAddress((void**)&pF2,  g_f2);

    size_t attSmem = (size_t)ATT_SMEM_FLOATS * sizeof(float);
    cudaFuncSetAttribute(attn_kernel, cudaFuncAttributeMaxDynamicSharedMemorySize, (int)attSmem);
    size_t tgSmem = (size_t)TG_SMEM_FLOATS * sizeof(float);
    cudaFuncSetAttribute(tgemm_kernel, cudaFuncAttributeMaxDynamicSharedMemorySize, (int)tgSmem);

    // 1. concat + positional embedding
    {
        size_t tot4 = (size_t)Bsz*Kk*Dm/4;
        concat_kernel<<<(unsigned)((tot4 + 255)/256), 256>>>(x, mem);
        size_t tot = (size_t)Kk*Dm;
        remb_kernel<<<(unsigned)((tot + 255)/256), 256>>>();
    }
    // 2. projections (tf32 tensor cores)
    tgemm_kernel<<<dim3(Dm/128, (Bsz*Tq)/128), 256, tgSmem>>>(x,   Wq, bq, pQ, Bsz*Tq, Dm, Dm, 0);
    tgemm_kernel<<<dim3(Dm/128, (Bsz*Kk)/128), 256, tgSmem>>>(pC,  Wk, bk, pK, Bsz*Kk, Dm, Dm, 0);
    tgemm_kernel<<<dim3(Dm/128, (Bsz*Kk)/128), 256, tgSmem>>>(pC,  Wv, bv, pV, Bsz*Kk, Dm, Dm, 0);
    tgemm_kernel<<<dim3(Dm/128, Kk/128),        256, tgSmem>>>(pRe, Wr, (const float*)nullptr, pR, Kk, Dm, Dm, 0);
    // 3. attention (tf32 mma)
    attn_kernel<<<dim3(Tq/64, Hh, Bsz), 256, attSmem>>>(pQ, pK, pV, pR, u, vv, pc, pAtt);
    // 4. output projection + LN1
    tgemm_kernel<<<dim3(Dm/128, (Bsz*Tq)/128), 256, tgSmem>>>(pAtt, Wo, bo, pProj, Bsz*Tq, Dm, Dm, 0);
    addln_kernel<<<Bsz*Tq, 256>>>(pProj, x, g1, be1, pH);
    // 5. FFN + LN2
    tgemm_kernel<<<dim3(Ff/128, (Bsz*Tq)/128), 256, tgSmem>>>(pH,   W1, b1, pFfn, Bsz*Tq, Ff, Dm, 1);
    tgemm_kernel<<<dim3(Dm/128, (Bsz*Tq)/128), 256, tgSmem>>>(pFfn, W2, b2, pF2,  Bsz*Tq, Dm, Ff, 0);
    addln_kernel<<<Bsz*Tq, 256>>>(pF2, pH, g2, be2, out);
}